// round 1
// baseline (speedup 1.0000x reference)
#include <cuda_runtime.h>
#include <math.h>
#include <math_constants.h>

#define N_TOK 4096
#define DMODEL 256
#define NHEAD 4
#define DHEAD 64
#define TOPK 30
#define SCALE 0.25f
#define LN_EPS 1e-5f

typedef unsigned long long ull;

// ---------------- scratch (static device allocations; no runtime alloc) ----------
__device__ float g_q[N_TOK * DMODEL];
__device__ float g_k[N_TOK * DMODEL];
__device__ float g_v[N_TOK * DMODEL];
__device__ float g_ctx[N_TOK * DMODEL];
__device__ float g_resid[N_TOK * DMODEL];

// ---------------- packed fp32x2 helpers (Blackwell f32x2 pipe) -------------------
__device__ __forceinline__ void fma2(ull& d, ull a, ull b) {
    asm("fma.rn.f32x2 %0, %1, %2, %0;" : "+l"(d) : "l"(a), "l"(b));
}
__device__ __forceinline__ float2 unpack2(ull v) {
    float2 f;
    asm("mov.b64 {%0, %1}, %2;" : "=f"(f.x), "=f"(f.y) : "l"(v));
    return f;
}

// ---------------- 64x64-tile fp32 GEMM body: C = A @ B^T (+bias)(+res) -----------
// A: [M,256] row-major, B: [256cols_out,256] row-major (nn.Linear weight)
// block: 256 threads, tile 64(M) x 64(Ncols), micro 4x4, K staged in 64-chunks.
template <bool ADD_RES>
__device__ __forceinline__ void gemm_body(const float* __restrict__ A,
                                          const float* __restrict__ B,
                                          const float* __restrict__ bias,
                                          const float* __restrict__ res,
                                          float* __restrict__ C) {
    __shared__ ull As[64 * 33];
    __shared__ ull Bs[64 * 33];
    const int tid = threadIdx.x;
    const int bm = blockIdx.y * 64;
    const int bn = blockIdx.x * 64;
    const int qg = (tid & 7) | ((tid >> 7) << 3);  // 0..15
    const int kg = (tid >> 3) & 15;                // 0..15

    ull acc[4][4];
#pragma unroll
    for (int a = 0; a < 4; ++a)
#pragma unroll
        for (int b = 0; b < 4; ++b) acc[a][b] = 0ull;

    for (int kk = 0; kk < 256; kk += 64) {
        __syncthreads();
#pragma unroll
        for (int i = 0; i < 8; ++i) {
            int idx = tid + i * 256;
            int r = idx >> 5, c = idx & 31;
            As[r * 33 + c] = *(const ull*)(A + (size_t)(bm + r) * 256 + kk + c * 2);
            Bs[r * 33 + c] = *(const ull*)(B + (size_t)(bn + r) * 256 + kk + c * 2);
        }
        __syncthreads();
#pragma unroll 8
        for (int d2 = 0; d2 < 32; ++d2) {
            ull qv[4], kv[4];
#pragma unroll
            for (int a = 0; a < 4; ++a) qv[a] = As[(qg * 4 + a) * 33 + d2];
#pragma unroll
            for (int b = 0; b < 4; ++b) kv[b] = Bs[(kg * 4 + b) * 33 + d2];
#pragma unroll
            for (int a = 0; a < 4; ++a)
#pragma unroll
                for (int b = 0; b < 4; ++b) fma2(acc[a][b], qv[a], kv[b]);
        }
    }
#pragma unroll
    for (int a = 0; a < 4; ++a) {
        int row = bm + qg * 4 + a;
#pragma unroll
        for (int b = 0; b < 4; ++b) {
            int col = bn + kg * 4 + b;
            float2 f = unpack2(acc[a][b]);
            float v = f.x + f.y + bias[col];
            if (ADD_RES) v += res[(size_t)row * 256 + col];
            C[(size_t)row * 256 + col] = v;
        }
    }
}

// ---------------- K1: fused Q/K/V projections (blockIdx.z selects matrix) --------
__global__ __launch_bounds__(256) void proj_kernel(
    const float* __restrict__ q_in, const float* __restrict__ k_in,
    const float* __restrict__ v_in, const float* __restrict__ Wq,
    const float* __restrict__ bq, const float* __restrict__ Wk,
    const float* __restrict__ bk, const float* __restrict__ Wv,
    const float* __restrict__ bv) {
    const float *A, *B, *bias;
    float* C;
    if (blockIdx.z == 0) { A = q_in; B = Wq; bias = bq; C = g_q; }
    else if (blockIdx.z == 1) { A = k_in; B = Wk; bias = bk; C = g_k; }
    else { A = v_in; B = Wv; bias = bv; C = g_v; }
    gemm_body<false>(A, B, bias, nullptr, C);
}

// ---------------- K2: scores + top-30 + softmax + attn write + sparse ctx --------
// grid: (64 q-blocks, 4 heads). block: 256 threads, 64 query rows.
__global__ __launch_bounds__(256) void attn_kernel(float* __restrict__ attn_out) {
    extern __shared__ char smem_raw[];
    ull* Qs = (ull*)smem_raw;          // 64 x 33 ull
    ull* Ks = Qs + 64 * 33;            // 64 x 33 ull
    float* Ss = (float*)(Ks + 64 * 33);  // 64 x 65 floats
    float* topv = Ss + 64 * 65;          // 64 x 30
    int* topi = (int*)(topv + 64 * TOPK);
    float* thr = (float*)(topi + 64 * TOPK);  // 64
    int* thrpos = (int*)(thr + 64);           // 64

    const int tid = threadIdx.x;
    const int h = blockIdx.y;
    const int qb = blockIdx.x * 64;
    const int qg = (tid & 7) | ((tid >> 7) << 3);
    const int kg = (tid >> 3) & 15;

// load Q tile (64 rows x 64 dims of this head)
#pragma unroll
    for (int i = 0; i < 8; ++i) {
        int idx = tid + i * 256;
        int r = idx >> 5, c = idx & 31;
        Qs[r * 33 + c] = *(const ull*)(g_q + (size_t)(qb + r) * 256 + h * 64 + c * 2);
    }
    if (tid < 64) {
        thr[tid] = -CUDART_INF_F;
        thrpos[tid] = 0;
        for (int j = 0; j < TOPK; ++j) {
            topv[tid * TOPK + j] = -CUDART_INF_F;
            topi[tid * TOPK + j] = 0x7FFFFFFF;
        }
    }

    for (int kt = 0; kt < 64; ++kt) {
        const int kb = kt * 64;
        __syncthreads();
#pragma unroll
        for (int i = 0; i < 8; ++i) {
            int idx = tid + i * 256;
            int r = idx >> 5, c = idx & 31;
            Ks[r * 33 + c] = *(const ull*)(g_k + (size_t)(kb + r) * 256 + h * 64 + c * 2);
        }
        __syncthreads();

        ull acc[4][4];
#pragma unroll
        for (int a = 0; a < 4; ++a)
#pragma unroll
            for (int b = 0; b < 4; ++b) acc[a][b] = 0ull;
#pragma unroll 8
        for (int d2 = 0; d2 < 32; ++d2) {
            ull qv[4], kv[4];
#pragma unroll
            for (int a = 0; a < 4; ++a) qv[a] = Qs[(qg * 4 + a) * 33 + d2];
#pragma unroll
            for (int b = 0; b < 4; ++b) kv[b] = Ks[(kg * 4 + b) * 33 + d2];
#pragma unroll
            for (int a = 0; a < 4; ++a)
#pragma unroll
                for (int b = 0; b < 4; ++b) fma2(acc[a][b], qv[a], kv[b]);
        }
#pragma unroll
        for (int a = 0; a < 4; ++a)
#pragma unroll
            for (int b = 0; b < 4; ++b) {
                float2 f = unpack2(acc[a][b]);
                Ss[(qg * 4 + a) * 65 + kg * 4 + b] = (f.x + f.y) * SCALE;
            }
        __syncthreads();

        // streaming top-30 selection: one thread per query row
        if (tid < 64) {
            const int r = tid;
            float th = thr[r];
            int tp = thrpos[r];
            float* tv = topv + r * TOPK;
            int* ti = topi + r * TOPK;
#pragma unroll 4
            for (int j = 0; j < 64; ++j) {
                float s = Ss[r * 65 + j];
                if (s > th) {
                    tv[tp] = s;
                    ti[tp] = kb + j;
                    float mn = tv[0];
                    int mp = 0, mi = ti[0];
#pragma unroll
                    for (int t = 1; t < TOPK; ++t) {
                        float v = tv[t];
                        int id = ti[t];
                        if (v < mn || (v == mn && id > mi)) { mn = v; mp = t; mi = id; }
                    }
                    th = mn;
                    tp = mp;
                }
            }
            thr[r] = th;
            thrpos[r] = tp;
        }
    }
    __syncthreads();

    // softmax over the 30 kept scores (per row)
    if (tid < 64) {
        float* tv = topv + tid * TOPK;
        float m = tv[0];
        for (int j = 1; j < TOPK; ++j) m = fmaxf(m, tv[j]);
        float s = 0.f;
        for (int j = 0; j < TOPK; ++j) {
            float e = expf(tv[j] - m);
            tv[j] = e;
            s += e;
        }
        float inv = 1.0f / s;
        for (int j = 0; j < TOPK; ++j) tv[j] *= inv;
    }
    __syncthreads();

    // dense-zero this block's 64 attn rows (1 MB), then scatter the 30 probs
    float* arow0 = attn_out + (size_t)(h * N_TOK + qb) * N_TOK;
    float4* a4 = (float4*)arow0;
    const float4 z4 = make_float4(0.f, 0.f, 0.f, 0.f);
    for (int i = tid; i < 64 * (N_TOK / 4); i += 256) a4[i] = z4;
    __syncthreads();
    if (tid < 64) {
        float* arow = arow0 + (size_t)tid * N_TOK;
        float* tv = topv + tid * TOPK;
        int* ti = topi + tid * TOPK;
        for (int j = 0; j < TOPK; ++j) arow[ti[j]] = tv[j];
    }

    // sparse ctx = sum_j p_j * V[idx_j]  (warp per 8 rows, lanes cover 64 dims)
    const int w = tid >> 5, lane = tid & 31;
    for (int i = 0; i < 8; ++i) {
        int r = w * 8 + i;
        float* tv = topv + r * TOPK;
        int* ti = topi + r * TOPK;
        float a0 = 0.f, a1 = 0.f;
        for (int j = 0; j < TOPK; ++j) {
            float p = tv[j];
            int m = ti[j];
            const float* vp = g_v + (size_t)m * 256 + h * 64;
            a0 += p * vp[lane];
            a1 += p * vp[lane + 32];
        }
        g_ctx[(size_t)(qb + r) * 256 + h * 64 + lane] = a0;
        g_ctx[(size_t)(qb + r) * 256 + h * 64 + lane + 32] = a1;
    }
}

// ---------------- K3: out-proj + residual -> g_resid -----------------------------
__global__ __launch_bounds__(256) void oproj_kernel(const float* __restrict__ Wo,
                                                    const float* __restrict__ bo,
                                                    const float* __restrict__ q_in) {
    gemm_body<true>(g_ctx, Wo, bo, q_in, g_resid);
}

// ---------------- K4: row LayerNorm -> d_out[0 : N*D] ----------------------------
__global__ __launch_bounds__(256) void ln_kernel(const float* __restrict__ g,
                                                 const float* __restrict__ b,
                                                 float* __restrict__ out) {
    const int row = blockIdx.x;
    const int tid = threadIdx.x;
    float x = g_resid[(size_t)row * 256 + tid];
    float s = x, s2 = x * x;
#pragma unroll
    for (int o = 16; o; o >>= 1) {
        s += __shfl_xor_sync(0xFFFFFFFFu, s, o);
        s2 += __shfl_xor_sync(0xFFFFFFFFu, s2, o);
    }
    __shared__ float rs[8], rs2[8];
    const int w = tid >> 5, lane = tid & 31;
    if (lane == 0) { rs[w] = s; rs2[w] = s2; }
    __syncthreads();
    float tot = 0.f, tot2 = 0.f;
#pragma unroll
    for (int i = 0; i < 8; ++i) { tot += rs[i]; tot2 += rs2[i]; }
    float mu = tot * (1.0f / 256.0f);
    float var = tot2 * (1.0f / 256.0f) - mu * mu;
    float inv = rsqrtf(var + LN_EPS);
    out[(size_t)row * 256 + tid] = (x - mu) * inv * g[tid] + b[tid];
}

// ---------------- launch ----------------------------------------------------------
extern "C" void kernel_launch(void* const* d_in, const int* in_sizes, int n_in,
                              void* d_out, int out_size) {
    const float* key_in   = (const float*)d_in[0];
    const float* value_in = (const float*)d_in[1];
    const float* query_in = (const float*)d_in[2];
    const float* Wq = (const float*)d_in[3];
    const float* bq = (const float*)d_in[4];
    const float* Wk = (const float*)d_in[5];
    const float* bk = (const float*)d_in[6];
    const float* Wv = (const float*)d_in[7];
    const float* bv = (const float*)d_in[8];
    const float* Wo = (const float*)d_in[9];
    const float* bo = (const float*)d_in[10];
    const float* ln_g = (const float*)d_in[11];
    const float* ln_b = (const float*)d_in[12];

    float* out = (float*)d_out;
    float* attn = out + (size_t)N_TOK * DMODEL;

    const int ATTN_SMEM = (64 * 33 * 8) * 2      // Qs + Ks
                        + 64 * 65 * 4            // Ss
                        + 64 * TOPK * 4 * 2      // topv + topi
                        + 64 * 4 * 2;            // thr + thrpos
    cudaFuncSetAttribute(attn_kernel, cudaFuncAttributeMaxDynamicSharedMemorySize,
                         ATTN_SMEM);

    // 1) Q/K/V projections
    proj_kernel<<<dim3(4, 64, 3), 256>>>(query_in, key_in, value_in, Wq, bq, Wk, bk,
                                         Wv, bv);
    // 2) scores + topk + softmax + attn + ctx
    attn_kernel<<<dim3(64, 4), 256, ATTN_SMEM>>>(attn);
    // 3) output projection + residual
    oproj_kernel<<<dim3(4, 64), 256>>>(Wo, bo, query_in);
    // 4) layernorm
    ln_kernel<<<N_TOK, 256>>>(ln_g, ln_b, out);
}

// round 2
// speedup vs baseline: 3.6908x; 3.6908x over previous
#include <cuda_runtime.h>
#include <math.h>
#include <math_constants.h>

#define N_TOK 4096
#define DMODEL 256
#define NHEAD 4
#define DHEAD 64
#define TOPK 30
#define SCALE 0.25f
#define LN_EPS 1e-5f

typedef unsigned long long ull;

// ---------------- scratch (static device allocations; no runtime alloc) ----------
__device__ float g_q[N_TOK * DMODEL];
__device__ float g_k[N_TOK * DMODEL];
__device__ float g_v[N_TOK * DMODEL];
__device__ float g_ctx[N_TOK * DMODEL];
__device__ float g_resid[N_TOK * DMODEL];

// ---------------- packed fp32x2 helpers (Blackwell f32x2 pipe) -------------------
__device__ __forceinline__ void fma2(ull& d, ull a, ull b) {
    asm("fma.rn.f32x2 %0, %1, %2, %0;" : "+l"(d) : "l"(a), "l"(b));
}
__device__ __forceinline__ float2 unpack2(ull v) {
    float2 f;
    asm("mov.b64 {%0, %1}, %2;" : "=f"(f.x), "=f"(f.y) : "l"(v));
    return f;
}
// monotone float->uint map (ascending)
__device__ __forceinline__ unsigned ford(float f) {
    unsigned u = __float_as_uint(f);
    return (u & 0x80000000u) ? ~u : (u | 0x80000000u);
}

// ---------------- 64x64-tile fp32 GEMM body: C = A @ B^T (+bias)(+res) -----------
template <bool ADD_RES>
__device__ __forceinline__ void gemm_body(const float* __restrict__ A,
                                          const float* __restrict__ B,
                                          const float* __restrict__ bias,
                                          const float* __restrict__ res,
                                          float* __restrict__ C) {
    __shared__ ull As[64 * 33];
    __shared__ ull Bs[64 * 33];
    const int tid = threadIdx.x;
    const int bm = blockIdx.y * 64;
    const int bn = blockIdx.x * 64;
    const int qg = (tid & 7) | ((tid >> 7) << 3);
    const int kg = (tid >> 3) & 15;

    ull acc[4][4];
#pragma unroll
    for (int a = 0; a < 4; ++a)
#pragma unroll
        for (int b = 0; b < 4; ++b) acc[a][b] = 0ull;

    for (int kk = 0; kk < 256; kk += 64) {
        __syncthreads();
#pragma unroll
        for (int i = 0; i < 8; ++i) {
            int idx = tid + i * 256;
            int r = idx >> 5, c = idx & 31;
            As[r * 33 + c] = *(const ull*)(A + (size_t)(bm + r) * 256 + kk + c * 2);
            Bs[r * 33 + c] = *(const ull*)(B + (size_t)(bn + r) * 256 + kk + c * 2);
        }
        __syncthreads();
#pragma unroll 8
        for (int d2 = 0; d2 < 32; ++d2) {
            ull qv[4], kv[4];
#pragma unroll
            for (int a = 0; a < 4; ++a) qv[a] = As[(qg * 4 + a) * 33 + d2];
#pragma unroll
            for (int b = 0; b < 4; ++b) kv[b] = Bs[(kg * 4 + b) * 33 + d2];
#pragma unroll
            for (int a = 0; a < 4; ++a)
#pragma unroll
                for (int b = 0; b < 4; ++b) fma2(acc[a][b], qv[a], kv[b]);
        }
    }
#pragma unroll
    for (int a = 0; a < 4; ++a) {
        int row = bm + qg * 4 + a;
#pragma unroll
        for (int b = 0; b < 4; ++b) {
            int col = bn + kg * 4 + b;
            float2 f = unpack2(acc[a][b]);
            float v = f.x + f.y + bias[col];
            if (ADD_RES) v += res[(size_t)row * 256 + col];
            C[(size_t)row * 256 + col] = v;
        }
    }
}

// ---------------- K1: fused Q/K/V projections -------------------------------------
__global__ __launch_bounds__(256) void proj_kernel(
    const float* __restrict__ q_in, const float* __restrict__ k_in,
    const float* __restrict__ v_in, const float* __restrict__ Wq,
    const float* __restrict__ bq, const float* __restrict__ Wk,
    const float* __restrict__ bk, const float* __restrict__ Wv,
    const float* __restrict__ bv) {
    const float *A, *B, *bias;
    float* C;
    if (blockIdx.z == 0) { A = q_in; B = Wq; bias = bq; C = g_q; }
    else if (blockIdx.z == 1) { A = k_in; B = Wk; bias = bk; C = g_k; }
    else { A = v_in; B = Wv; bias = bv; C = g_v; }
    gemm_body<false>(A, B, bias, nullptr, C);
}

// ---------------- K2a: dense score GEMM -> attn buffer (scaled) -------------------
// grid: (64 kb, 32 qb, 4 h). block 256. tile 128(q) x 64(k). micro 8x4 in ull.
// smem XOR-swizzled: conflict-free operand loads.
__global__ __launch_bounds__(256, 2) void score_kernel(float* __restrict__ attn) {
    __shared__ ull Qs[128 * 32];
    __shared__ ull Ks[64 * 32];
    const int tid = threadIdx.x;
    const int h = blockIdx.z;
    const int qb0 = blockIdx.y * 128;
    const int kb0 = blockIdx.x * 64;
    const int kg = tid & 15;   // 16 col-groups of 4
    const int qg = tid >> 4;   // 16 row-groups of 8

    // fill Q tile: 4096 ull, swizzle c ^ (r>>3)
#pragma unroll
    for (int i = 0; i < 16; ++i) {
        int idx = tid + i * 256;
        int r = idx >> 5, c = idx & 31;
        Qs[(r << 5) | (c ^ (r >> 3))] =
            *(const ull*)(g_q + (size_t)(qb0 + r) * 256 + h * 64 + c * 2);
    }
    // fill K tile: 2048 ull, swizzle c ^ (r>>2)
#pragma unroll
    for (int i = 0; i < 8; ++i) {
        int idx = tid + i * 256;
        int r = idx >> 5, c = idx & 31;
        Ks[(r << 5) | (c ^ (r >> 2))] =
            *(const ull*)(g_k + (size_t)(kb0 + r) * 256 + h * 64 + c * 2);
    }
    __syncthreads();

    ull acc[8][4];
#pragma unroll
    for (int a = 0; a < 8; ++a)
#pragma unroll
        for (int b = 0; b < 4; ++b) acc[a][b] = 0ull;

#pragma unroll 4
    for (int d2 = 0; d2 < 32; ++d2) {
        ull qv[8], kv[4];
#pragma unroll
        for (int a = 0; a < 8; ++a) qv[a] = Qs[((qg * 8 + a) << 5) | (d2 ^ qg)];
#pragma unroll
        for (int b = 0; b < 4; ++b) kv[b] = Ks[((kg * 4 + b) << 5) | (d2 ^ kg)];
#pragma unroll
        for (int a = 0; a < 8; ++a)
#pragma unroll
            for (int b = 0; b < 4; ++b) fma2(acc[a][b], qv[a], kv[b]);
    }

#pragma unroll
    for (int a = 0; a < 8; ++a) {
        int row = qb0 + qg * 8 + a;
        float4 o;
        float2 f0 = unpack2(acc[a][0]);
        float2 f1 = unpack2(acc[a][1]);
        float2 f2 = unpack2(acc[a][2]);
        float2 f3 = unpack2(acc[a][3]);
        o.x = (f0.x + f0.y) * SCALE;
        o.y = (f1.x + f1.y) * SCALE;
        o.z = (f2.x + f2.y) * SCALE;
        o.w = (f3.x + f3.y) * SCALE;
        *(float4*)(attn + ((size_t)(h * N_TOK + row)) * N_TOK + kb0 + kg * 4) = o;
    }
}

// ---------------- K2b: warp-per-row top-30 + softmax + rewrite + sparse ctx -------
__global__ __launch_bounds__(256) void topk_kernel(float* __restrict__ attn) {
    const unsigned FULL = 0xFFFFFFFFu;
    const int warp = threadIdx.x >> 5, lane = threadIdx.x & 31;
    const int row = blockIdx.x * 8 + warp;  // 0..16383  (= h*4096 + n)
    const int h = row >> 12;
    const int n = row & 4095;
    float* arow = attn + (size_t)row * N_TOK;
    const float4* p4 = (const float4*)arow;

    // distributed top-30 list in lanes 0..29
    unsigned lu = 0u;          // ordered-bits value; 0 is below any real score
    int li = 0x7FFFFFFF;
    unsigned wu = 0u;          // current worst (value bits)
    int wi = 0x7FFFFFFF;       // current worst index
    int wslot = 0;             // lane holding the worst

    for (int c = 0; c < 32; ++c) {
        float4 v = p4[c * 32 + lane];
#pragma unroll
        for (int j = 0; j < 4; ++j) {
            float s = (j == 0) ? v.x : (j == 1) ? v.y : (j == 2) ? v.z : v.w;
            unsigned cu = ford(s);
            int ci = c * 128 + lane * 4 + j;
            unsigned m = __ballot_sync(FULL, (cu > wu) || (cu == wu && ci < wi));
            while (m) {
                int src = __ffs(m) - 1;
                m &= m - 1;
                unsigned c2 = __shfl_sync(FULL, cu, src);
                int i2 = __shfl_sync(FULL, ci, src);
                if ((c2 > wu) || (c2 == wu && i2 < wi)) {
                    if (lane == wslot) { lu = c2; li = i2; }
                    unsigned ku = (lane < TOPK) ? lu : 0xFFFFFFFFu;
                    wu = __reduce_min_sync(FULL, ku);
                    unsigned wim =
                        __reduce_max_sync(FULL, (ku == wu) ? (unsigned)li : 0u);
                    wi = (int)wim;
                    unsigned bs =
                        __ballot_sync(FULL, ku == wu && (unsigned)li == wim);
                    wslot = __ffs(bs) - 1;
                }
            }
        }
    }

    // softmax over the 30 kept scores
    float lv = (lane < TOPK) ? __uint_as_float((lu & 0x80000000u) ? (lu & 0x7FFFFFFFu)
                                                                  : ~lu)
                             : -CUDART_INF_F;
    // max via ordered-bits reduce
    unsigned mx = __reduce_max_sync(FULL, (lane < TOPK) ? lu : 0u);
    float mval = __uint_as_float((mx & 0x80000000u) ? (mx & 0x7FFFFFFFu) : ~mx);
    float e = (lane < TOPK) ? expf(lv - mval) : 0.f;
    float ssum = e;
#pragma unroll
    for (int o = 16; o; o >>= 1) ssum += __shfl_xor_sync(FULL, ssum, o);
    float p = e / ssum;

    // rewrite row: zeros then scatter
    float4* w4 = (float4*)arow;
    const float4 z4 = make_float4(0.f, 0.f, 0.f, 0.f);
#pragma unroll 4
    for (int c = lane; c < N_TOK / 4; c += 32) w4[c] = z4;
    __syncwarp();
    if (lane < TOPK) arow[li] = p;

    // sparse ctx: ctx[n, h*64 + 2*lane .. +1] = sum_j p_j * V[idx_j]
    float2 acc = make_float2(0.f, 0.f);
    const float* vbase = g_v + h * 64 + 2 * lane;
#pragma unroll 6
    for (int j = 0; j < TOPK; ++j) {
        float pj = __shfl_sync(FULL, p, j);
        int ij = __shfl_sync(FULL, li, j);
        float2 vv = *(const float2*)(vbase + (size_t)ij * 256);
        acc.x += pj * vv.x;
        acc.y += pj * vv.y;
    }
    *(float2*)(g_ctx + (size_t)n * 256 + h * 64 + 2 * lane) = acc;
}

// ---------------- K3: out-proj + residual -> g_resid ------------------------------
__global__ __launch_bounds__(256) void oproj_kernel(const float* __restrict__ Wo,
                                                    const float* __restrict__ bo,
                                                    const float* __restrict__ q_in) {
    gemm_body<true>(g_ctx, Wo, bo, q_in, g_resid);
}

// ---------------- K4: row LayerNorm -> d_out[0 : N*D] -----------------------------
__global__ __launch_bounds__(256) void ln_kernel(const float* __restrict__ g,
                                                 const float* __restrict__ b,
                                                 float* __restrict__ out) {
    const int row = blockIdx.x;
    const int tid = threadIdx.x;
    float x = g_resid[(size_t)row * 256 + tid];
    float s = x, s2 = x * x;
#pragma unroll
    for (int o = 16; o; o >>= 1) {
        s += __shfl_xor_sync(0xFFFFFFFFu, s, o);
        s2 += __shfl_xor_sync(0xFFFFFFFFu, s2, o);
    }
    __shared__ float rs[8], rs2[8];
    const int w = tid >> 5, lane = tid & 31;
    if (lane == 0) { rs[w] = s; rs2[w] = s2; }
    __syncthreads();
    float tot = 0.f, tot2 = 0.f;
#pragma unroll
    for (int i = 0; i < 8; ++i) { tot += rs[i]; tot2 += rs2[i]; }
    float mu = tot * (1.0f / 256.0f);
    float var = tot2 * (1.0f / 256.0f) - mu * mu;
    float inv = rsqrtf(var + LN_EPS);
    out[(size_t)row * 256 + tid] = (x - mu) * inv * g[tid] + b[tid];
}

// ---------------- launch -----------------------------------------------------------
extern "C" void kernel_launch(void* const* d_in, const int* in_sizes, int n_in,
                              void* d_out, int out_size) {
    const float* key_in   = (const float*)d_in[0];
    const float* value_in = (const float*)d_in[1];
    const float* query_in = (const float*)d_in[2];
    const float* Wq = (const float*)d_in[3];
    const float* bq = (const float*)d_in[4];
    const float* Wk = (const float*)d_in[5];
    const float* bk = (const float*)d_in[6];
    const float* Wv = (const float*)d_in[7];
    const float* bv = (const float*)d_in[8];
    const float* Wo = (const float*)d_in[9];
    const float* bo = (const float*)d_in[10];
    const float* ln_g = (const float*)d_in[11];
    const float* ln_b = (const float*)d_in[12];

    float* out = (float*)d_out;
    float* attn = out + (size_t)N_TOK * DMODEL;

    // 1) Q/K/V projections
    proj_kernel<<<dim3(4, 64, 3), 256>>>(query_in, key_in, value_in, Wq, bq, Wk, bk,
                                         Wv, bv);
    // 2a) dense scaled scores into attn buffer (scratch)
    score_kernel<<<dim3(64, 32, 4), 256>>>(attn);
    // 2b) per-row top-30, softmax, rewrite attn, sparse ctx
    topk_kernel<<<N_TOK * NHEAD / 8, 256>>>(attn);
    // 3) output projection + residual
    oproj_kernel<<<dim3(4, 64), 256>>>(Wo, bo, query_in);
    // 4) layernorm
    ln_kernel<<<N_TOK, 256>>>(ln_g, ln_b, out);
}